// round 10
// baseline (speedup 1.0000x reference)
#include <cuda_runtime.h>
#include <cuda_bf16.h>
#include <mma.h>
#include <math.h>
#include <stdint.h>

using namespace nvcuda;

#define TOKENS 4096
#define HIDDEN 2048
#define INTER  1408
#define NE     16
#define TOPK   2
#define MAXROWS (TOKENS * TOPK)

// ---------------- scratch (proven envelope: small statics, <48K smem) ----------
__device__ int   g_count[NE];
__device__ int   g_offset[NE + 1];
__device__ int   g_cursor[NE];
__device__ int   g_te[TOKENS * TOPK];
__device__ float g_tw[TOKENS * TOPK];
__device__ int   g_tok[MAXROWS];
__device__ float g_w[MAXROWS];
__device__ __align__(128) __nv_bfloat16 g_ahi[(size_t)MAXROWS * INTER];
__device__ __align__(128) __nv_bfloat16 g_alo[(size_t)MAXROWS * INTER];

// ---------------- helpers ------------------------------------------------------
__device__ __forceinline__ void split4s(float4 v,
                                        __nv_bfloat16* hp, __nv_bfloat16* lp) {
    __nv_bfloat162 h01 = __floats2bfloat162_rn(v.x, v.y);
    __nv_bfloat162 h23 = __floats2bfloat162_rn(v.z, v.w);
    float2 f01 = __bfloat1622float2(h01);
    float2 f23 = __bfloat1622float2(h23);
    __nv_bfloat162 l01 = __floats2bfloat162_rn(v.x - f01.x, v.y - f01.y);
    __nv_bfloat162 l23 = __floats2bfloat162_rn(v.z - f23.x, v.w - f23.y);
    *(uint2*)hp = make_uint2(*(uint32_t*)&h01, *(uint32_t*)&h23);
    *(uint2*)lp = make_uint2(*(uint32_t*)&l01, *(uint32_t*)&l23);
}

typedef wmma::fragment<wmma::matrix_a, 16, 16, 16, __nv_bfloat16, wmma::row_major> FragA;
typedef wmma::fragment<wmma::matrix_b, 16, 16, 16, __nv_bfloat16, wmma::row_major> FragB;
typedef wmma::fragment<wmma::accumulator, 16, 16, 16, float> FragC;

// ---------------- routing kernels ------------------------------------------------
__global__ void route_kernel(const float* __restrict__ logits) {
    int t = blockIdx.x * blockDim.x + threadIdx.x;
    if (t >= TOKENS) return;
    const float* l = logits + (size_t)t * NE;
    int i0 = 0; float m0 = l[0];
#pragma unroll
    for (int i = 1; i < NE; i++) { float x = l[i]; if (x > m0) { m0 = x; i0 = i; } }
    int i1 = (i0 == 0) ? 1 : 0; float m1 = l[i1];
#pragma unroll
    for (int i = 0; i < NE; i++) {
        if (i == i0) continue;
        float x = l[i];
        if (x > m1) { m1 = x; i1 = i; }
    }
    float e  = expf(m1 - m0);
    float w0 = 1.0f / (1.0f + e);
    float w1 = e * w0;
    g_te[t * 2 + 0] = i0;  g_tw[t * 2 + 0] = w0;
    g_te[t * 2 + 1] = i1;  g_tw[t * 2 + 1] = w1;
}

// counts + scan + cursor init in one block (no pre-zero kernel needed)
__global__ __launch_bounds__(1024) void scan_kernel() {
    __shared__ int s_cnt[NE];
    const int tid = threadIdx.x;
    if (tid < NE) s_cnt[tid] = 0;
    __syncthreads();
    for (int i = tid; i < MAXROWS; i += 1024) atomicAdd(&s_cnt[g_te[i]], 1);
    __syncthreads();
    if (tid == 0) {
        int acc = 0;
        for (int e = 0; e < NE; e++) {
            g_count[e]  = s_cnt[e];
            g_offset[e] = acc;
            acc += s_cnt[e];
            g_cursor[e] = 0;
        }
        g_offset[NE] = acc;
    }
}

__global__ void place_kernel() {
    int t = blockIdx.x * blockDim.x + threadIdx.x;
    if (t >= TOKENS) return;
#pragma unroll
    for (int k = 0; k < TOPK; k++) {
        int   e = g_te[t * 2 + k];
        float w = g_tw[t * 2 + k];
        int pos = atomicAdd(&g_cursor[e], 1);
        int idx = g_offset[e] + pos;
        g_tok[idx] = t;
        g_w[idx]   = w;
    }
}

__global__ void zero_kernel(float* __restrict__ out) {
    int i = blockIdx.x * blockDim.x + threadIdx.x;
    if (i < TOKENS * HIDDEN) out[i] = 0.0f;
}

// ================ GEMM1: gate+up, wmma bf16x3, BK=16, dist-2 prefetch ===========
#define LDA 24
#define LDB 72
#define G1_STG  21504
#define G1_SMEM (512 + 2 * G1_STG)

__global__ __launch_bounds__(256) void gemm1_wmma(
    const float* __restrict__ hid,
    const float* __restrict__ wg,
    const float* __restrict__ wu)
{
    const int e   = blockIdx.z;
    const int cnt = g_count[e];
    const int m0  = blockIdx.y * 128;
    if (m0 >= cnt) return;
    const int n0   = blockIdx.x * 64;
    const int base = g_offset[e];

    extern __shared__ char sm[];
    int* toks = (int*)sm;

    const int tid  = threadIdx.x;
    const int wid  = tid >> 5, lane = tid & 31;
    const int wm   = (wid & 3) * 32;
    const int wn   = (wid >> 2) * 32;

    if (tid < 128) {
        int r = m0 + tid;
        toks[tid] = g_tok[base + ((r < cnt) ? r : 0)];
    }
    __syncthreads();

    FragC accg[2][2], accu[2][2];
#pragma unroll
    for (int mt = 0; mt < 2; mt++)
#pragma unroll
        for (int nt = 0; nt < 2; nt++) {
            wmma::fill_fragment(accg[mt][nt], 0.0f);
            wmma::fill_fragment(accu[mt][nt], 0.0f);
        }

    const int ar0 = tid >> 2,        ac0 = (tid & 3) * 4;
    const int ar1 = (tid + 256) >> 2;
    const int brow = tid >> 4,       bc4 = (tid & 15) * 4;
    const float* arow0 = hid + (size_t)toks[ar0] * HIDDEN + ac0;
    const float* arow1 = hid + (size_t)toks[ar1] * HIDDEN + ac0;

    auto LOADG = [&](int k0, float4& A0, float4& A1, float4& G, float4& U) {
        A0 = *(const float4*)(arow0 + k0);
        A1 = *(const float4*)(arow1 + k0);
        size_t off = (size_t)e * HIDDEN * INTER + (size_t)(k0 + brow) * INTER + n0 + bc4;
        G = *(const float4*)(wg + off);
        U = *(const float4*)(wu + off);
    };
    auto STORES = [&](int b, float4 A0, float4 A1, float4 G, float4 U) {
        char* st = sm + 512 + b * G1_STG;
        __nv_bfloat16* Ahi = (__nv_bfloat16*)(st);
        __nv_bfloat16* Alo = (__nv_bfloat16*)(st + 6144);
        __nv_bfloat16* Bgh = (__nv_bfloat16*)(st + 12288);
        __nv_bfloat16* Bgl = (__nv_bfloat16*)(st + 14592);
        __nv_bfloat16* Buh = (__nv_bfloat16*)(st + 16896);
        __nv_bfloat16* Bul = (__nv_bfloat16*)(st + 19200);
        split4s(A0, Ahi + ar0 * LDA + ac0, Alo + ar0 * LDA + ac0);
        split4s(A1, Ahi + ar1 * LDA + ac0, Alo + ar1 * LDA + ac0);
        split4s(G,  Bgh + brow * LDB + bc4, Bgl + brow * LDB + bc4);
        split4s(U,  Buh + brow * LDB + bc4, Bul + brow * LDB + bc4);
    };
    auto COMPUTE = [&](int b) {
        const char* st = sm + 512 + b * G1_STG;
        const __nv_bfloat16* Ahi = (const __nv_bfloat16*)(st);
        const __nv_bfloat16* Alo = (const __nv_bfloat16*)(st + 6144);
        const __nv_bfloat16* Bgh = (const __nv_bfloat16*)(st + 12288);
        const __nv_bfloat16* Bgl = (const __nv_bfloat16*)(st + 14592);
        const __nv_bfloat16* Buh = (const __nv_bfloat16*)(st + 16896);
        const __nv_bfloat16* Bul = (const __nv_bfloat16*)(st + 19200);
        FragA ah[2], al[2];
#pragma unroll
        for (int mt = 0; mt < 2; mt++) {
            wmma::load_matrix_sync(ah[mt], Ahi + (wm + mt * 16) * LDA, LDA);
            wmma::load_matrix_sync(al[mt], Alo + (wm + mt * 16) * LDA, LDA);
        }
#pragma unroll
        for (int nt = 0; nt < 2; nt++) {
            FragB bh, bl;
            const int bcol = wn + nt * 16;
            wmma::load_matrix_sync(bh, Bgh + bcol, LDB);
            wmma::load_matrix_sync(bl, Bgl + bcol, LDB);
#pragma unroll
            for (int mt = 0; mt < 2; mt++) {
                wmma::mma_sync(accg[mt][nt], ah[mt], bh, accg[mt][nt]);
                wmma::mma_sync(accg[mt][nt], al[mt], bh, accg[mt][nt]);
                wmma::mma_sync(accg[mt][nt], ah[mt], bl, accg[mt][nt]);
            }
            wmma::load_matrix_sync(bh, Buh + bcol, LDB);
            wmma::load_matrix_sync(bl, Bul + bcol, LDB);
#pragma unroll
            for (int mt = 0; mt < 2; mt++) {
                wmma::mma_sync(accu[mt][nt], ah[mt], bh, accu[mt][nt]);
                wmma::mma_sync(accu[mt][nt], al[mt], bh, accu[mt][nt]);
                wmma::mma_sync(accu[mt][nt], ah[mt], bl, accu[mt][nt]);
            }
        }
    };

    const int NS = HIDDEN / 16;   // 128 (even)
    float4 A0a, A1a, Ga, Ua, A0b, A1b, Gb, Ub;
    LOADG(0,  A0a, A1a, Ga, Ua);
    LOADG(16, A0b, A1b, Gb, Ub);
    STORES(0, A0a, A1a, Ga, Ua);
    LOADG(32, A0a, A1a, Ga, Ua);
    __syncthreads();

    for (int s = 0; s < NS; s += 2) {
        if (s + 1 < NS) STORES(1, A0b, A1b, Gb, Ub);
        if (s + 3 < NS) LOADG((s + 3) * 16, A0b, A1b, Gb, Ub);
        COMPUTE(0);
        __syncthreads();
        if (s + 2 < NS) STORES(0, A0a, A1a, Ga, Ua);
        if (s + 4 < NS) LOADG((s + 4) * 16, A0a, A1a, Ga, Ua);
        COMPUTE(1);
        __syncthreads();
    }

    // epilogue: swiglu + bf16 hi/lo activation store
    float* stg = (float*)(sm + 512) + wid * 320;
#pragma unroll
    for (int mt = 0; mt < 2; mt++)
#pragma unroll
        for (int nt = 0; nt < 2; nt++) {
            FragC& G = accg[mt][nt];
            FragC& U = accu[mt][nt];
#pragma unroll
            for (int i = 0; i < G.num_elements; i++) {
                float g = G.x[i];
                G.x[i] = (g / (1.0f + __expf(-g))) * U.x[i];
            }
            wmma::store_matrix_sync(stg, G, 20, wmma::mem_row_major);
            __syncwarp();
            for (int i = lane; i < 128; i += 32) {
                int r = i >> 3, c = (i & 7) * 2;
                int m = m0 + wm + mt * 16 + r;
                if (m < cnt) {
                    float a0 = stg[r * 20 + c], a1 = stg[r * 20 + c + 1];
                    __nv_bfloat162 hv = __floats2bfloat162_rn(a0, a1);
                    float2 hf = __bfloat1622float2(hv);
                    __nv_bfloat162 lv = __floats2bfloat162_rn(a0 - hf.x, a1 - hf.y);
                    size_t off = (size_t)(base + m) * INTER + n0 + wn + nt * 16 + c;
                    *(__nv_bfloat162*)(g_ahi + off) = hv;
                    *(__nv_bfloat162*)(g_alo + off) = lv;
                }
            }
            __syncwarp();
        }
}

// ================ GEMM2: down, wmma bf16x3, BN=128, BK=16, dist-2 prefetch ======
// Stage: Ahi 6144 | Alo 6144 | Bh 4352 | Bl 4352 = 20992; x2 = 41984 < 48K
#define LDB2 136
#define G2_STG  20992
#define G2_SMEM (2 * G2_STG)

__global__ __launch_bounds__(256) void gemm2_wmma(
    const float* __restrict__ wd, float* __restrict__ out)
{
    const int e   = blockIdx.z;
    const int cnt = g_count[e];
    const int m0  = blockIdx.y * 128;
    if (m0 >= cnt) return;
    const int n0   = blockIdx.x * 128;
    const int base = g_offset[e];

    extern __shared__ char sm[];

    const int tid  = threadIdx.x;
    const int wid  = tid >> 5, lane = tid & 31;
    const int wm   = (wid & 3) * 32;
    const int wn   = (wid >> 2) * 64;

    // A loader: 128 rows x 16 bf16 (hi+lo), 1 uint4 pair per thread
    const int ar = tid >> 1;
    const int aq = (tid & 1) * 8;
    int arm = m0 + ar;
    const int arow = base + ((arm < cnt) ? arm : 0);
    // B loader: 16 rows x 128 fp32, 2 float4 per thread
    const int brow = tid >> 4, bc8 = (tid & 15) * 8;

    FragC acc[2][4];
#pragma unroll
    for (int mt = 0; mt < 2; mt++)
#pragma unroll
        for (int nt = 0; nt < 4; nt++) wmma::fill_fragment(acc[mt][nt], 0.0f);

    auto LOADG = [&](int k0, uint4& Ah, uint4& Al, float4& B0, float4& B1) {
        size_t off = (size_t)arow * INTER + k0 + aq;
        Ah = *(const uint4*)(g_ahi + off);
        Al = *(const uint4*)(g_alo + off);
        const float* bsrc = wd + (size_t)e * INTER * HIDDEN + (size_t)(k0 + brow) * HIDDEN + n0 + bc8;
        B0 = *(const float4*)(bsrc);
        B1 = *(const float4*)(bsrc + 4);
    };
    auto STORES = [&](int b, uint4 Ah, uint4 Al, float4 B0, float4 B1) {
        char* st = sm + b * G2_STG;
        __nv_bfloat16* Ahi = (__nv_bfloat16*)(st);
        __nv_bfloat16* Alo = (__nv_bfloat16*)(st + 6144);
        __nv_bfloat16* Bh  = (__nv_bfloat16*)(st + 12288);
        __nv_bfloat16* Bl  = (__nv_bfloat16*)(st + 16640);
        *(uint4*)(Ahi + ar * LDA + aq) = Ah;
        *(uint4*)(Alo + ar * LDA + aq) = Al;
        split4s(B0, Bh + brow * LDB2 + bc8,     Bl + brow * LDB2 + bc8);
        split4s(B1, Bh + brow * LDB2 + bc8 + 4, Bl + brow * LDB2 + bc8 + 4);
    };
    auto COMPUTE = [&](int b) {
        const char* st = sm + b * G2_STG;
        const __nv_bfloat16* Ahi = (const __nv_bfloat16*)(st);
        const __nv_bfloat16* Alo = (const __nv_bfloat16*)(st + 6144);
        const __nv_bfloat16* Bh  = (const __nv_bfloat16*)(st + 12288);
        const __nv_bfloat16* Bl  = (const __nv_bfloat16*)(st + 16640);
        FragA ah[2], al[2];
#pragma unroll
        for (int mt = 0; mt < 2; mt++) {
            wmma::load_matrix_sync(ah[mt], Ahi + (wm + mt * 16) * LDA, LDA);
            wmma::load_matrix_sync(al[mt], Alo + (wm + mt * 16) * LDA, LDA);
        }
#pragma unroll
        for (int nt = 0; nt < 4; nt++) {
            FragB bh, bl;
            const int bcol = wn + nt * 16;
            wmma::load_matrix_sync(bh, Bh + bcol, LDB2);
            wmma::load_matrix_sync(bl, Bl + bcol, LDB2);
#pragma unroll
            for (int mt = 0; mt < 2; mt++) {
                wmma::mma_sync(acc[mt][nt], ah[mt], bh, acc[mt][nt]);
                wmma::mma_sync(acc[mt][nt], al[mt], bh, acc[mt][nt]);
                wmma::mma_sync(acc[mt][nt], ah[mt], bl, acc[mt][nt]);
            }
        }
    };

    const int NS = INTER / 16;   // 88 (even)
    uint4 Aha, Ala, Ahb, Alb;
    float4 B0a, B1a, B0b, B1b;
    LOADG(0,  Aha, Ala, B0a, B1a);
    LOADG(16, Ahb, Alb, B0b, B1b);
    STORES(0, Aha, Ala, B0a, B1a);
    LOADG(32, Aha, Ala, B0a, B1a);
    __syncthreads();

    for (int s = 0; s < NS; s += 2) {
        if (s + 1 < NS) STORES(1, Ahb, Alb, B0b, B1b);
        if (s + 3 < NS) LOADG((s + 3) * 16, Ahb, Alb, B0b, B1b);
        COMPUTE(0);
        __syncthreads();
        if (s + 2 < NS) STORES(0, Aha, Ala, B0a, B1a);
        if (s + 4 < NS) LOADG((s + 4) * 16, Aha, Ala, B0a, B1a);
        COMPUTE(1);
        __syncthreads();
    }

    // weighted scatter via per-warp staging
    float* stg = (float*)sm + wid * 320;
#pragma unroll
    for (int mt = 0; mt < 2; mt++)
#pragma unroll
        for (int nt = 0; nt < 4; nt++) {
            wmma::store_matrix_sync(stg, acc[mt][nt], 20, wmma::mem_row_major);
            __syncwarp();
            for (int i = lane; i < 256; i += 32) {
                int r = i >> 4, c = i & 15;
                int m = m0 + wm + mt * 16 + r;
                if (m < cnt) {
                    int   t = g_tok[base + m];
                    float w = g_w[base + m];
                    atomicAdd(out + (size_t)t * HIDDEN + n0 + wn + nt * 16 + c,
                              w * stg[r * 20 + c]);
                }
            }
            __syncwarp();
        }
}

// ---------------- launch ------------------------------------------------------------
extern "C" void kernel_launch(void* const* d_in, const int* in_sizes, int n_in,
                              void* d_out, int out_size) {
    (void)in_sizes; (void)n_in; (void)out_size;
    const float* hidden = (const float*)d_in[0];
    const float* logits = (const float*)d_in[1];
    const float* wg     = (const float*)d_in[2];
    const float* wu     = (const float*)d_in[3];
    const float* wd     = (const float*)d_in[4];
    float* out = (float*)d_out;

    route_kernel<<<(TOKENS + 255) / 256, 256>>>(logits);                 // 0
    scan_kernel<<<1, 1024>>>();                                          // 1
    place_kernel<<<(TOKENS + 255) / 256, 256>>>();                       // 2

    dim3 g1(INTER / 64, (TOKENS + 127) / 128, NE);    // (22, 32, 16)
    gemm1_wmma<<<g1, 256, G1_SMEM>>>(hidden, wg, wu);                    // 3 (global 5?)

    zero_kernel<<<(TOKENS * HIDDEN + 255) / 256, 256>>>(out);            // 4
    dim3 g2(HIDDEN / 128, (TOKENS + 127) / 128, NE);  // (16, 32, 16)
    gemm2_wmma<<<g2, 256, G2_SMEM>>>(wd, out);                           // 5
}

// round 11
// speedup vs baseline: 1.1480x; 1.1480x over previous
#include <cuda_runtime.h>
#include <cuda_bf16.h>
#include <mma.h>
#include <math.h>
#include <stdint.h>

using namespace nvcuda;

#define TOKENS 4096
#define HIDDEN 2048
#define INTER  1408
#define NE     16
#define TOPK   2
#define MAXROWS (TOKENS * TOPK)

// ---------------- scratch (proven envelope) -------------------------------------
__device__ int   g_count[NE];
__device__ int   g_offset[NE + 1];
__device__ int   g_cursor[NE];
__device__ int   g_te[TOKENS * TOPK];
__device__ float g_tw[TOKENS * TOPK];
__device__ int   g_tok[MAXROWS];
__device__ float g_w[MAXROWS];
__device__ __align__(128) __nv_bfloat16 g_ahi[(size_t)MAXROWS * INTER];
__device__ __align__(128) __nv_bfloat16 g_alo[(size_t)MAXROWS * INTER];

// ---------------- helpers ------------------------------------------------------
__device__ __forceinline__ void split4s(float4 v,
                                        __nv_bfloat16* hp, __nv_bfloat16* lp) {
    __nv_bfloat162 h01 = __floats2bfloat162_rn(v.x, v.y);
    __nv_bfloat162 h23 = __floats2bfloat162_rn(v.z, v.w);
    float2 f01 = __bfloat1622float2(h01);
    float2 f23 = __bfloat1622float2(h23);
    __nv_bfloat162 l01 = __floats2bfloat162_rn(v.x - f01.x, v.y - f01.y);
    __nv_bfloat162 l23 = __floats2bfloat162_rn(v.z - f23.x, v.w - f23.y);
    *(uint2*)hp = make_uint2(*(uint32_t*)&h01, *(uint32_t*)&h23);
    *(uint2*)lp = make_uint2(*(uint32_t*)&l01, *(uint32_t*)&l23);
}

typedef wmma::fragment<wmma::matrix_a, 16, 16, 16, __nv_bfloat16, wmma::row_major> FragA;
typedef wmma::fragment<wmma::matrix_b, 16, 16, 16, __nv_bfloat16, wmma::row_major> FragB;
typedef wmma::fragment<wmma::accumulator, 16, 16, 16, float> FragC;

// ---------------- routing kernels ------------------------------------------------
__global__ void route_kernel(const float* __restrict__ logits) {
    int t = blockIdx.x * blockDim.x + threadIdx.x;
    if (t >= TOKENS) return;
    const float* l = logits + (size_t)t * NE;
    int i0 = 0; float m0 = l[0];
#pragma unroll
    for (int i = 1; i < NE; i++) { float x = l[i]; if (x > m0) { m0 = x; i0 = i; } }
    int i1 = (i0 == 0) ? 1 : 0; float m1 = l[i1];
#pragma unroll
    for (int i = 0; i < NE; i++) {
        if (i == i0) continue;
        float x = l[i];
        if (x > m1) { m1 = x; i1 = i; }
    }
    float e  = expf(m1 - m0);
    float w0 = 1.0f / (1.0f + e);
    float w1 = e * w0;
    g_te[t * 2 + 0] = i0;  g_tw[t * 2 + 0] = w0;
    g_te[t * 2 + 1] = i1;  g_tw[t * 2 + 1] = w1;
}

__global__ __launch_bounds__(1024) void scan_kernel() {
    __shared__ int s_cnt[NE];
    const int tid = threadIdx.x;
    if (tid < NE) s_cnt[tid] = 0;
    __syncthreads();
    for (int i = tid; i < MAXROWS; i += 1024) atomicAdd(&s_cnt[g_te[i]], 1);
    __syncthreads();
    if (tid == 0) {
        int acc = 0;
        for (int e = 0; e < NE; e++) {
            g_count[e]  = s_cnt[e];
            g_offset[e] = acc;
            acc += s_cnt[e];
            g_cursor[e] = 0;
        }
        g_offset[NE] = acc;
    }
}

__global__ void place_kernel() {
    int t = blockIdx.x * blockDim.x + threadIdx.x;
    if (t >= TOKENS) return;
#pragma unroll
    for (int k = 0; k < TOPK; k++) {
        int   e = g_te[t * 2 + k];
        float w = g_tw[t * 2 + k];
        int pos = atomicAdd(&g_cursor[e], 1);
        int idx = g_offset[e] + pos;
        g_tok[idx] = t;
        g_w[idx]   = w;
    }
}

__global__ void zero_kernel(float* __restrict__ out) {
    int i = blockIdx.x * blockDim.x + threadIdx.x;
    if (i < TOKENS * HIDDEN) out[i] = 0.0f;
}

// ================ GEMM1: gate+up, wmma bf16x3, BK=16, 2-stage, 2 CTAs/SM ========
#define LDA 24
#define LDB 72
#define G1_STG  21504
#define G1_SMEM (512 + 2 * G1_STG)

__global__ __launch_bounds__(256, 2) void gemm1_wmma(
    const float* __restrict__ hid,
    const float* __restrict__ wg,
    const float* __restrict__ wu)
{
    const int e   = blockIdx.z;
    const int cnt = g_count[e];
    const int m0  = blockIdx.y * 128;
    if (m0 >= cnt) return;
    const int n0   = blockIdx.x * 64;
    const int base = g_offset[e];

    extern __shared__ char sm[];
    int* toks = (int*)sm;

    const int tid  = threadIdx.x;
    const int wid  = tid >> 5, lane = tid & 31;
    const int wm   = (wid & 3) * 32;
    const int wn   = (wid >> 2) * 32;

    if (tid < 128) {
        int r = m0 + tid;
        toks[tid] = g_tok[base + ((r < cnt) ? r : 0)];
    }
    __syncthreads();

    FragC accg[2][2], accu[2][2];
#pragma unroll
    for (int mt = 0; mt < 2; mt++)
#pragma unroll
        for (int nt = 0; nt < 2; nt++) {
            wmma::fill_fragment(accg[mt][nt], 0.0f);
            wmma::fill_fragment(accu[mt][nt], 0.0f);
        }

    const int ar0 = tid >> 2,  ac0 = (tid & 3) * 4;
    const int ar1 = (tid + 256) >> 2;
    const int brow = tid >> 4, bc4 = (tid & 15) * 4;
    const float* arow0 = hid + (size_t)toks[ar0] * HIDDEN + ac0;
    const float* arow1 = hid + (size_t)toks[ar1] * HIDDEN + ac0;

    float4 pfA0, pfA1, pfG, pfU;

    auto LOADG = [&](int k0) {
        pfA0 = *(const float4*)(arow0 + k0);
        pfA1 = *(const float4*)(arow1 + k0);
        size_t off = (size_t)e * HIDDEN * INTER + (size_t)(k0 + brow) * INTER + n0 + bc4;
        pfG = *(const float4*)(wg + off);
        pfU = *(const float4*)(wu + off);
    };
    auto STORES = [&](int b) {
        char* st = sm + 512 + b * G1_STG;
        __nv_bfloat16* Ahi = (__nv_bfloat16*)(st);
        __nv_bfloat16* Alo = (__nv_bfloat16*)(st + 6144);
        __nv_bfloat16* Bgh = (__nv_bfloat16*)(st + 12288);
        __nv_bfloat16* Bgl = (__nv_bfloat16*)(st + 14592);
        __nv_bfloat16* Buh = (__nv_bfloat16*)(st + 16896);
        __nv_bfloat16* Bul = (__nv_bfloat16*)(st + 19200);
        split4s(pfA0, Ahi + ar0 * LDA + ac0, Alo + ar0 * LDA + ac0);
        split4s(pfA1, Ahi + ar1 * LDA + ac0, Alo + ar1 * LDA + ac0);
        split4s(pfG,  Bgh + brow * LDB + bc4, Bgl + brow * LDB + bc4);
        split4s(pfU,  Buh + brow * LDB + bc4, Bul + brow * LDB + bc4);
    };

    const int NS = HIDDEN / 16;   // 128
    LOADG(0);
    STORES(0);
    LOADG(16);
    __syncthreads();

    for (int s = 0; s < NS; s++) {
        if (s + 1 < NS) STORES((s + 1) & 1);
        if (s + 2 < NS) LOADG((s + 2) * 16);

        const char* st = sm + 512 + (s & 1) * G1_STG;
        const __nv_bfloat16* Ahi = (const __nv_bfloat16*)(st);
        const __nv_bfloat16* Alo = (const __nv_bfloat16*)(st + 6144);
        const __nv_bfloat16* Bgh = (const __nv_bfloat16*)(st + 12288);
        const __nv_bfloat16* Bgl = (const __nv_bfloat16*)(st + 14592);
        const __nv_bfloat16* Buh = (const __nv_bfloat16*)(st + 16896);
        const __nv_bfloat16* Bul = (const __nv_bfloat16*)(st + 19200);

        FragA ah[2], al[2];
#pragma unroll
        for (int mt = 0; mt < 2; mt++) {
            wmma::load_matrix_sync(ah[mt], Ahi + (wm + mt * 16) * LDA, LDA);
            wmma::load_matrix_sync(al[mt], Alo + (wm + mt * 16) * LDA, LDA);
        }
#pragma unroll
        for (int nt = 0; nt < 2; nt++) {
            FragB bh, bl;
            const int bcol = wn + nt * 16;
            wmma::load_matrix_sync(bh, Bgh + bcol, LDB);
            wmma::load_matrix_sync(bl, Bgl + bcol, LDB);
#pragma unroll
            for (int mt = 0; mt < 2; mt++) {
                wmma::mma_sync(accg[mt][nt], ah[mt], bh, accg[mt][nt]);
                wmma::mma_sync(accg[mt][nt], al[mt], bh, accg[mt][nt]);
                wmma::mma_sync(accg[mt][nt], ah[mt], bl, accg[mt][nt]);
            }
            wmma::load_matrix_sync(bh, Buh + bcol, LDB);
            wmma::load_matrix_sync(bl, Bul + bcol, LDB);
#pragma unroll
            for (int mt = 0; mt < 2; mt++) {
                wmma::mma_sync(accu[mt][nt], ah[mt], bh, accu[mt][nt]);
                wmma::mma_sync(accu[mt][nt], al[mt], bh, accu[mt][nt]);
                wmma::mma_sync(accu[mt][nt], ah[mt], bl, accu[mt][nt]);
            }
        }
        __syncthreads();
    }

    // epilogue: swiglu + bf16 hi/lo activation store
    float* stg = (float*)(sm + 512) + wid * 320;
#pragma unroll
    for (int mt = 0; mt < 2; mt++)
#pragma unroll
        for (int nt = 0; nt < 2; nt++) {
            FragC& G = accg[mt][nt];
            FragC& U = accu[mt][nt];
#pragma unroll
            for (int i = 0; i < G.num_elements; i++) {
                float g = G.x[i];
                G.x[i] = (g / (1.0f + __expf(-g))) * U.x[i];
            }
            wmma::store_matrix_sync(stg, G, 20, wmma::mem_row_major);
            __syncwarp();
            for (int i = lane; i < 128; i += 32) {
                int r = i >> 3, c = (i & 7) * 2;
                int m = m0 + wm + mt * 16 + r;
                if (m < cnt) {
                    float a0 = stg[r * 20 + c], a1 = stg[r * 20 + c + 1];
                    __nv_bfloat162 hv = __floats2bfloat162_rn(a0, a1);
                    float2 hf = __bfloat1622float2(hv);
                    __nv_bfloat162 lv = __floats2bfloat162_rn(a0 - hf.x, a1 - hf.y);
                    size_t off = (size_t)(base + m) * INTER + n0 + wn + nt * 16 + c;
                    *(__nv_bfloat162*)(g_ahi + off) = hv;
                    *(__nv_bfloat162*)(g_alo + off) = lv;
                }
            }
            __syncwarp();
        }
}

// ================ GEMM2: down, wmma bf16x3, BK=16, 2-stage, 2 CTAs/SM ===========
#define G2_STG  16896
#define G2_SMEM (2 * G2_STG)

__global__ __launch_bounds__(256, 2) void gemm2_wmma(
    const float* __restrict__ wd, float* __restrict__ out)
{
    const int e   = blockIdx.z;
    const int cnt = g_count[e];
    const int m0  = blockIdx.y * 128;
    if (m0 >= cnt) return;
    const int n0   = blockIdx.x * 64;
    const int base = g_offset[e];

    extern __shared__ char sm[];

    const int tid  = threadIdx.x;
    const int wid  = tid >> 5, lane = tid & 31;
    const int wm   = (wid & 3) * 32;
    const int wn   = (wid >> 2) * 32;

    const int ar = tid >> 1;
    const int aq = (tid & 1) * 8;
    int arm = m0 + ar;
    const int arow = base + ((arm < cnt) ? arm : 0);
    const int brow = tid >> 4, bc4 = (tid & 15) * 4;

    FragC acc[2][2];
#pragma unroll
    for (int mt = 0; mt < 2; mt++)
#pragma unroll
        for (int nt = 0; nt < 2; nt++) wmma::fill_fragment(acc[mt][nt], 0.0f);

    uint4 pfAh, pfAl;
    float4 pfB;

    auto LOADG = [&](int k0) {
        size_t off = (size_t)arow * INTER + k0 + aq;
        pfAh = *(const uint4*)(g_ahi + off);
        pfAl = *(const uint4*)(g_alo + off);
        pfB  = *(const float4*)(wd + (size_t)e * INTER * HIDDEN +
                                (size_t)(k0 + brow) * HIDDEN + n0 + bc4);
    };
    auto STORES = [&](int b) {
        char* st = sm + b * G2_STG;
        __nv_bfloat16* Ahi = (__nv_bfloat16*)(st);
        __nv_bfloat16* Alo = (__nv_bfloat16*)(st + 6144);
        __nv_bfloat16* Bh  = (__nv_bfloat16*)(st + 12288);
        __nv_bfloat16* Bl  = (__nv_bfloat16*)(st + 14592);
        *(uint4*)(Ahi + ar * LDA + aq) = pfAh;
        *(uint4*)(Alo + ar * LDA + aq) = pfAl;
        split4s(pfB, Bh + brow * LDB + bc4, Bl + brow * LDB + bc4);
    };

    const int NS = INTER / 16;   // 88
    LOADG(0);
    STORES(0);
    LOADG(16);
    __syncthreads();

    for (int s = 0; s < NS; s++) {
        if (s + 1 < NS) STORES((s + 1) & 1);
        if (s + 2 < NS) LOADG((s + 2) * 16);

        const char* st = sm + (s & 1) * G2_STG;
        const __nv_bfloat16* Ahi = (const __nv_bfloat16*)(st);
        const __nv_bfloat16* Alo = (const __nv_bfloat16*)(st + 6144);
        const __nv_bfloat16* Bh  = (const __nv_bfloat16*)(st + 12288);
        const __nv_bfloat16* Bl  = (const __nv_bfloat16*)(st + 14592);

        FragA ah[2], al[2];
#pragma unroll
        for (int mt = 0; mt < 2; mt++) {
            wmma::load_matrix_sync(ah[mt], Ahi + (wm + mt * 16) * LDA, LDA);
            wmma::load_matrix_sync(al[mt], Alo + (wm + mt * 16) * LDA, LDA);
        }
#pragma unroll
        for (int nt = 0; nt < 2; nt++) {
            FragB bh, bl;
            const int bcol = wn + nt * 16;
            wmma::load_matrix_sync(bh, Bh + bcol, LDB);
            wmma::load_matrix_sync(bl, Bl + bcol, LDB);
#pragma unroll
            for (int mt = 0; mt < 2; mt++) {
                wmma::mma_sync(acc[mt][nt], ah[mt], bh, acc[mt][nt]);
                wmma::mma_sync(acc[mt][nt], al[mt], bh, acc[mt][nt]);
                wmma::mma_sync(acc[mt][nt], ah[mt], bl, acc[mt][nt]);
            }
        }
        __syncthreads();
    }

    // weighted scatter via per-warp staging
    float* stg = (float*)sm + wid * 320;
#pragma unroll
    for (int mt = 0; mt < 2; mt++)
#pragma unroll
        for (int nt = 0; nt < 2; nt++) {
            wmma::store_matrix_sync(stg, acc[mt][nt], 20, wmma::mem_row_major);
            __syncwarp();
            for (int i = lane; i < 256; i += 32) {
                int r = i >> 4, c = i & 15;
                int m = m0 + wm + mt * 16 + r;
                if (m < cnt) {
                    int   t = g_tok[base + m];
                    float w = g_w[base + m];
                    atomicAdd(out + (size_t)t * HIDDEN + n0 + wn + nt * 16 + c,
                              w * stg[r * 20 + c]);
                }
            }
            __syncwarp();
        }
}

// ---------------- launch ------------------------------------------------------------
extern "C" void kernel_launch(void* const* d_in, const int* in_sizes, int n_in,
                              void* d_out, int out_size) {
    (void)in_sizes; (void)n_in; (void)out_size;
    const float* hidden = (const float*)d_in[0];
    const float* logits = (const float*)d_in[1];
    const float* wg     = (const float*)d_in[2];
    const float* wu     = (const float*)d_in[3];
    const float* wd     = (const float*)d_in[4];
    float* out = (float*)d_out;

    route_kernel<<<(TOKENS + 255) / 256, 256>>>(logits);                 // 0
    scan_kernel<<<1, 1024>>>();                                          // 1
    place_kernel<<<(TOKENS + 255) / 256, 256>>>();                       // 2

    dim3 g1(INTER / 64, (TOKENS + 127) / 128, NE);    // (22, 32, 16)
    gemm1_wmma<<<g1, 256, G1_SMEM>>>(hidden, wg, wu);                    // 3

    zero_kernel<<<(TOKENS * HIDDEN + 255) / 256, 256>>>(out);            // 4
    dim3 g2(HIDDEN / 64, (TOKENS + 127) / 128, NE);   // (32, 32, 16)
    gemm2_wmma<<<g2, 256, G2_SMEM>>>(wd, out);                           // 5
}

// round 12
// speedup vs baseline: 1.2206x; 1.0632x over previous
#include <cuda_runtime.h>
#include <cuda_bf16.h>
#include <mma.h>
#include <math.h>
#include <stdint.h>

using namespace nvcuda;

#define TOKENS 4096
#define HIDDEN 2048
#define INTER  1408
#define NE     16
#define TOPK   2
#define MAXROWS (TOKENS * TOPK)

// ---------------- scratch ----------------------------------------------------
__device__ int   g_count[NE];
__device__ int   g_offset[NE + 1];
__device__ int   g_te[TOKENS * TOPK];
__device__ float g_tw[TOKENS * TOPK];
__device__ int   g_tok[MAXROWS];
__device__ float g_w[MAXROWS];
// hidden pre-split to bf16 hi/lo (33.5 MB)
__device__ __align__(128) __nv_bfloat16 g_hhi[(size_t)TOKENS * HIDDEN];
__device__ __align__(128) __nv_bfloat16 g_hlo[(size_t)TOKENS * HIDDEN];
// activations bf16 hi/lo (46 MB)
__device__ __align__(128) __nv_bfloat16 g_ahi[(size_t)MAXROWS * INTER];
__device__ __align__(128) __nv_bfloat16 g_alo[(size_t)MAXROWS * INTER];

// ---------------- helpers ------------------------------------------------------
__device__ __forceinline__ void split4s(float4 v,
                                        __nv_bfloat16* hp, __nv_bfloat16* lp) {
    __nv_bfloat162 h01 = __floats2bfloat162_rn(v.x, v.y);
    __nv_bfloat162 h23 = __floats2bfloat162_rn(v.z, v.w);
    float2 f01 = __bfloat1622float2(h01);
    float2 f23 = __bfloat1622float2(h23);
    __nv_bfloat162 l01 = __floats2bfloat162_rn(v.x - f01.x, v.y - f01.y);
    __nv_bfloat162 l23 = __floats2bfloat162_rn(v.z - f23.x, v.w - f23.y);
    *(uint2*)hp = make_uint2(*(uint32_t*)&h01, *(uint32_t*)&h23);
    *(uint2*)lp = make_uint2(*(uint32_t*)&l01, *(uint32_t*)&l23);
}

typedef wmma::fragment<wmma::matrix_a, 16, 16, 16, __nv_bfloat16, wmma::row_major> FragA;
typedef wmma::fragment<wmma::matrix_b, 16, 16, 16, __nv_bfloat16, wmma::row_major> FragB;
typedef wmma::fragment<wmma::accumulator, 16, 16, 16, float> FragC;

// ---------------- kernel 0: routing ---------------------------------------------
__global__ void route_kernel(const float* __restrict__ logits) {
    int t = blockIdx.x * blockDim.x + threadIdx.x;
    if (t >= TOKENS) return;
    const float* l = logits + (size_t)t * NE;
    int i0 = 0; float m0 = l[0];
#pragma unroll
    for (int i = 1; i < NE; i++) { float x = l[i]; if (x > m0) { m0 = x; i0 = i; } }
    int i1 = (i0 == 0) ? 1 : 0; float m1 = l[i1];
#pragma unroll
    for (int i = 0; i < NE; i++) {
        if (i == i0) continue;
        float x = l[i];
        if (x > m1) { m1 = x; i1 = i; }
    }
    float e  = expf(m1 - m0);
    float w0 = 1.0f / (1.0f + e);
    float w1 = e * w0;
    g_te[t * 2 + 0] = i0;  g_tw[t * 2 + 0] = w0;
    g_te[t * 2 + 1] = i1;  g_tw[t * 2 + 1] = w1;
}

// ---------------- kernel 1: count + scan + place (one block) --------------------
__global__ __launch_bounds__(1024) void scanplace_kernel() {
    __shared__ int s_cnt[NE], s_off[NE], s_cur[NE];
    const int tid = threadIdx.x;
    if (tid < NE) s_cnt[tid] = 0;
    __syncthreads();
    for (int i = tid; i < MAXROWS; i += 1024) atomicAdd(&s_cnt[g_te[i]], 1);
    __syncthreads();
    if (tid == 0) {
        int acc = 0;
        for (int e = 0; e < NE; e++) {
            s_off[e] = acc;
            g_count[e]  = s_cnt[e];
            g_offset[e] = acc;
            acc += s_cnt[e];
        }
        g_offset[NE] = acc;
    }
    __syncthreads();
    if (tid < NE) s_cur[tid] = 0;
    __syncthreads();
    for (int i = tid; i < MAXROWS; i += 1024) {
        int e = g_te[i];
        int pos = atomicAdd(&s_cur[e], 1);
        int idx = s_off[e] + pos;
        g_tok[idx] = i >> 1;          // token id
        g_w[idx]   = g_tw[i];
    }
}

// ---------------- kernel 2: hidden fp32 -> bf16 hi/lo ----------------------------
__global__ void conv_hidden(const float4* __restrict__ src) {
    int i = blockIdx.x * blockDim.x + threadIdx.x;
    if (i >= TOKENS * HIDDEN / 4) return;
    float4 v = src[i];
    __nv_bfloat162 h01 = __floats2bfloat162_rn(v.x, v.y);
    __nv_bfloat162 h23 = __floats2bfloat162_rn(v.z, v.w);
    float2 f01 = __bfloat1622float2(h01);
    float2 f23 = __bfloat1622float2(h23);
    ((__nv_bfloat162*)g_hhi)[2 * i]     = h01;
    ((__nv_bfloat162*)g_hhi)[2 * i + 1] = h23;
    ((__nv_bfloat162*)g_hlo)[2 * i]     = __floats2bfloat162_rn(v.x - f01.x, v.y - f01.y);
    ((__nv_bfloat162*)g_hlo)[2 * i + 1] = __floats2bfloat162_rn(v.z - f23.x, v.w - f23.y);
}

__global__ void zero_kernel(float* __restrict__ out) {
    int i = blockIdx.x * blockDim.x + threadIdx.x;
    if (i < TOKENS * HIDDEN) out[i] = 0.0f;
}

// ================ GEMM1: gate+up, wmma bf16x3, BK=16, 2-stage, 2 CTAs/SM ========
// A path now pre-split bf16 (pure copy); only B needs in-loop splits.
#define LDA 24
#define LDB 72
#define G1_STG  21504
#define G1_SMEM (512 + 2 * G1_STG)

__global__ __launch_bounds__(256, 2) void gemm1_wmma(
    const float* __restrict__ wg,
    const float* __restrict__ wu)
{
    const int e   = blockIdx.z;
    const int cnt = g_count[e];
    const int m0  = blockIdx.y * 128;
    if (m0 >= cnt) return;
    const int n0   = blockIdx.x * 64;
    const int base = g_offset[e];

    extern __shared__ char sm[];
    int* toks = (int*)sm;

    const int tid  = threadIdx.x;
    const int wid  = tid >> 5, lane = tid & 31;
    const int wm   = (wid & 3) * 32;
    const int wn   = (wid >> 2) * 32;

    if (tid < 128) {
        int r = m0 + tid;
        toks[tid] = g_tok[base + ((r < cnt) ? r : 0)];
    }
    __syncthreads();

    FragC accg[2][2], accu[2][2];
#pragma unroll
    for (int mt = 0; mt < 2; mt++)
#pragma unroll
        for (int nt = 0; nt < 2; nt++) {
            wmma::fill_fragment(accg[mt][nt], 0.0f);
            wmma::fill_fragment(accu[mt][nt], 0.0f);
        }

    // A loader: 1 slot/thread: row ar (0..127), 8-elem chunk aq (0 or 8)
    const int ar = tid >> 1;
    const int aq = (tid & 1) * 8;
    const size_t arowoff = (size_t)toks[ar] * HIDDEN + aq;
    // B loader: 16 rows x 64 fp32, 1 float4/thread per matrix
    const int brow = tid >> 4, bc4 = (tid & 15) * 4;

    uint4 pfAh, pfAl;
    float4 pfG, pfU;

    auto LOADG = [&](int k0) {
        pfAh = *(const uint4*)(g_hhi + arowoff + k0);
        pfAl = *(const uint4*)(g_hlo + arowoff + k0);
        size_t off = (size_t)e * HIDDEN * INTER + (size_t)(k0 + brow) * INTER + n0 + bc4;
        pfG = *(const float4*)(wg + off);
        pfU = *(const float4*)(wu + off);
    };
    auto STORES = [&](int b) {
        char* st = sm + 512 + b * G1_STG;
        __nv_bfloat16* Ahi = (__nv_bfloat16*)(st);
        __nv_bfloat16* Alo = (__nv_bfloat16*)(st + 6144);
        __nv_bfloat16* Bgh = (__nv_bfloat16*)(st + 12288);
        __nv_bfloat16* Bgl = (__nv_bfloat16*)(st + 14592);
        __nv_bfloat16* Buh = (__nv_bfloat16*)(st + 16896);
        __nv_bfloat16* Bul = (__nv_bfloat16*)(st + 19200);
        *(uint4*)(Ahi + ar * LDA + aq) = pfAh;
        *(uint4*)(Alo + ar * LDA + aq) = pfAl;
        split4s(pfG, Bgh + brow * LDB + bc4, Bgl + brow * LDB + bc4);
        split4s(pfU, Buh + brow * LDB + bc4, Bul + brow * LDB + bc4);
    };

    const int NS = HIDDEN / 16;   // 128
    LOADG(0);
    STORES(0);
    LOADG(16);
    __syncthreads();

    for (int s = 0; s < NS; s++) {
        if (s + 1 < NS) STORES((s + 1) & 1);
        if (s + 2 < NS) LOADG((s + 2) * 16);

        const char* st = sm + 512 + (s & 1) * G1_STG;
        const __nv_bfloat16* Ahi = (const __nv_bfloat16*)(st);
        const __nv_bfloat16* Alo = (const __nv_bfloat16*)(st + 6144);
        const __nv_bfloat16* Bgh = (const __nv_bfloat16*)(st + 12288);
        const __nv_bfloat16* Bgl = (const __nv_bfloat16*)(st + 14592);
        const __nv_bfloat16* Buh = (const __nv_bfloat16*)(st + 16896);
        const __nv_bfloat16* Bul = (const __nv_bfloat16*)(st + 19200);

        FragA ah[2], al[2];
#pragma unroll
        for (int mt = 0; mt < 2; mt++) {
            wmma::load_matrix_sync(ah[mt], Ahi + (wm + mt * 16) * LDA, LDA);
            wmma::load_matrix_sync(al[mt], Alo + (wm + mt * 16) * LDA, LDA);
        }
#pragma unroll
        for (int nt = 0; nt < 2; nt++) {
            FragB bh, bl;
            const int bcol = wn + nt * 16;
            wmma::load_matrix_sync(bh, Bgh + bcol, LDB);
            wmma::load_matrix_sync(bl, Bgl + bcol, LDB);
#pragma unroll
            for (int mt = 0; mt < 2; mt++) {
                wmma::mma_sync(accg[mt][nt], ah[mt], bh, accg[mt][nt]);
                wmma::mma_sync(accg[mt][nt], al[mt], bh, accg[mt][nt]);
                wmma::mma_sync(accg[mt][nt], ah[mt], bl, accg[mt][nt]);
            }
            wmma::load_matrix_sync(bh, Buh + bcol, LDB);
            wmma::load_matrix_sync(bl, Bul + bcol, LDB);
#pragma unroll
            for (int mt = 0; mt < 2; mt++) {
                wmma::mma_sync(accu[mt][nt], ah[mt], bh, accu[mt][nt]);
                wmma::mma_sync(accu[mt][nt], al[mt], bh, accu[mt][nt]);
                wmma::mma_sync(accu[mt][nt], ah[mt], bl, accu[mt][nt]);
            }
        }
        __syncthreads();
    }

    // epilogue: swiglu + bf16 hi/lo activation store
    float* stg = (float*)(sm + 512) + wid * 320;
#pragma unroll
    for (int mt = 0; mt < 2; mt++)
#pragma unroll
        for (int nt = 0; nt < 2; nt++) {
            FragC& G = accg[mt][nt];
            FragC& U = accu[mt][nt];
#pragma unroll
            for (int i = 0; i < G.num_elements; i++) {
                float g = G.x[i];
                G.x[i] = (g / (1.0f + __expf(-g))) * U.x[i];
            }
            wmma::store_matrix_sync(stg, G, 20, wmma::mem_row_major);
            __syncwarp();
            for (int i = lane; i < 128; i += 32) {
                int r = i >> 3, c = (i & 7) * 2;
                int m = m0 + wm + mt * 16 + r;
                if (m < cnt) {
                    float a0 = stg[r * 20 + c], a1 = stg[r * 20 + c + 1];
                    __nv_bfloat162 hv = __floats2bfloat162_rn(a0, a1);
                    float2 hf = __bfloat1622float2(hv);
                    __nv_bfloat162 lv = __floats2bfloat162_rn(a0 - hf.x, a1 - hf.y);
                    size_t off = (size_t)(base + m) * INTER + n0 + wn + nt * 16 + c;
                    *(__nv_bfloat162*)(g_ahi + off) = hv;
                    *(__nv_bfloat162*)(g_alo + off) = lv;
                }
            }
            __syncwarp();
        }
}

// ================ GEMM2: down, wmma bf16x3, BN=128, BK=16, 2 CTAs/SM ============
// Stage: Ahi 6144 | Alo 6144 | Bh 4352 | Bl 4352 = 20992; x2 = 41984 < 48K
#define LDB2 136
#define G2_STG  20992
#define G2_SMEM (2 * G2_STG)

__global__ __launch_bounds__(256, 2) void gemm2_wmma(
    const float* __restrict__ wd, float* __restrict__ out)
{
    const int e   = blockIdx.z;
    const int cnt = g_count[e];
    const int m0  = blockIdx.y * 128;
    if (m0 >= cnt) return;
    const int n0   = blockIdx.x * 128;
    const int base = g_offset[e];

    extern __shared__ char sm[];

    const int tid  = threadIdx.x;
    const int wid  = tid >> 5, lane = tid & 31;
    const int wm   = (wid & 3) * 32;
    const int wn   = (wid >> 2) * 64;

    const int ar = tid >> 1;
    const int aq = (tid & 1) * 8;
    int arm = m0 + ar;
    const int arow = base + ((arm < cnt) ? arm : 0);
    const int brow = tid >> 4, bc8 = (tid & 15) * 8;

    FragC acc[2][4];
#pragma unroll
    for (int mt = 0; mt < 2; mt++)
#pragma unroll
        for (int nt = 0; nt < 4; nt++) wmma::fill_fragment(acc[mt][nt], 0.0f);

    uint4 pfAh, pfAl;
    float4 pfB0, pfB1;

    auto LOADG = [&](int k0) {
        size_t off = (size_t)arow * INTER + k0 + aq;
        pfAh = *(const uint4*)(g_ahi + off);
        pfAl = *(const uint4*)(g_alo + off);
        const float* bsrc = wd + (size_t)e * INTER * HIDDEN + (size_t)(k0 + brow) * HIDDEN + n0 + bc8;
        pfB0 = *(const float4*)(bsrc);
        pfB1 = *(const float4*)(bsrc + 4);
    };
    auto STORES = [&](int b) {
        char* st = sm + b * G2_STG;
        __nv_bfloat16* Ahi = (__nv_bfloat16*)(st);
        __nv_bfloat16* Alo = (__nv_bfloat16*)(st + 6144);
        __nv_bfloat16* Bh  = (__nv_bfloat16*)(st + 12288);
        __nv_bfloat16* Bl  = (__nv_bfloat16*)(st + 16640);
        *(uint4*)(Ahi + ar * LDA + aq) = pfAh;
        *(uint4*)(Alo + ar * LDA + aq) = pfAl;
        split4s(pfB0, Bh + brow * LDB2 + bc8,     Bl + brow * LDB2 + bc8);
        split4s(pfB1, Bh + brow * LDB2 + bc8 + 4, Bl + brow * LDB2 + bc8 + 4);
    };

    const int NS = INTER / 16;   // 88
    LOADG(0);
    STORES(0);
    LOADG(16);
    __syncthreads();

    for (int s = 0; s < NS; s++) {
        if (s + 1 < NS) STORES((s + 1) & 1);
        if (s + 2 < NS) LOADG((s + 2) * 16);

        const char* st = sm + (s & 1) * G2_STG;
        const __nv_bfloat16* Ahi = (const __nv_bfloat16*)(st);
        const __nv_bfloat16* Alo = (const __nv_bfloat16*)(st + 6144);
        const __nv_bfloat16* Bh  = (const __nv_bfloat16*)(st + 12288);
        const __nv_bfloat16* Bl  = (const __nv_bfloat16*)(st + 16640);

        FragA ah[2], al[2];
#pragma unroll
        for (int mt = 0; mt < 2; mt++) {
            wmma::load_matrix_sync(ah[mt], Ahi + (wm + mt * 16) * LDA, LDA);
            wmma::load_matrix_sync(al[mt], Alo + (wm + mt * 16) * LDA, LDA);
        }
#pragma unroll
        for (int nt = 0; nt < 4; nt++) {
            FragB bh, bl;
            const int bcol = wn + nt * 16;
            wmma::load_matrix_sync(bh, Bh + bcol, LDB2);
            wmma::load_matrix_sync(bl, Bl + bcol, LDB2);
#pragma unroll
            for (int mt = 0; mt < 2; mt++) {
                wmma::mma_sync(acc[mt][nt], ah[mt], bh, acc[mt][nt]);
                wmma::mma_sync(acc[mt][nt], al[mt], bh, acc[mt][nt]);
                wmma::mma_sync(acc[mt][nt], ah[mt], bl, acc[mt][nt]);
            }
        }
        __syncthreads();
    }

    // weighted scatter via per-warp staging
    float* stg = (float*)sm + wid * 320;
#pragma unroll
    for (int mt = 0; mt < 2; mt++)
#pragma unroll
        for (int nt = 0; nt < 4; nt++) {
            wmma::store_matrix_sync(stg, acc[mt][nt], 20, wmma::mem_row_major);
            __syncwarp();
            for (int i = lane; i < 256; i += 32) {
                int r = i >> 4, c = i & 15;
                int m = m0 + wm + mt * 16 + r;
                if (m < cnt) {
                    int   t = g_tok[base + m];
                    float w = g_w[base + m];
                    atomicAdd(out + (size_t)t * HIDDEN + n0 + wn + nt * 16 + c,
                              w * stg[r * 20 + c]);
                }
            }
            __syncwarp();
        }
}

// ---------------- launch ------------------------------------------------------------
extern "C" void kernel_launch(void* const* d_in, const int* in_sizes, int n_in,
                              void* d_out, int out_size) {
    (void)in_sizes; (void)n_in; (void)out_size;
    const float* hidden = (const float*)d_in[0];
    const float* logits = (const float*)d_in[1];
    const float* wg     = (const float*)d_in[2];
    const float* wu     = (const float*)d_in[3];
    const float* wd     = (const float*)d_in[4];
    float* out = (float*)d_out;

    route_kernel<<<(TOKENS + 255) / 256, 256>>>(logits);                  // 0
    scanplace_kernel<<<1, 1024>>>();                                      // 1
    conv_hidden<<<(TOKENS * HIDDEN / 4 + 255) / 256, 256>>>((const float4*)hidden); // 2

    dim3 g1(INTER / 64, (TOKENS + 127) / 128, NE);    // (22, 32, 16)
    gemm1_wmma<<<g1, 256, G1_SMEM>>>(wg, wu);                             // 3 (global 5)

    zero_kernel<<<(TOKENS * HIDDEN + 255) / 256, 256>>>(out);             // 4
    dim3 g2(HIDDEN / 128, (TOKENS + 127) / 128, NE);  // (16, 32, 16)
    gemm2_wmma<<<g2, 256, G2_SMEM>>>(wd, out);                            // 5
}